// round 7
// baseline (speedup 1.0000x reference)
#include <cuda_runtime.h>
#include <cstdint>

#define N_DIM 1024
#define M_DIM 2048
#define P_DIM 512
#define Q_DIM 128
#define KAPPA 0.99f
#define TOL   3e-6f
#define SWITCH_MD 1e-3f
#define MAXIT 300
#define NBLK  256

#define KC   16
#define LDA  20
// smem floats: Ah[2][64*LDA]=2560, Al=2560, Xh[2][128*LDA]=5120, Xl=5120
#define SM_AL 2560
#define SM_XH 5120
#define SM_XL 10240
#define DSMEM_BYTES (15360 * 4)

// ---------------- device state ----------------
__device__ float g_Ahi[(size_t)N_DIM * N_DIM];
__device__ float g_Alo[(size_t)N_DIM * N_DIM];
__device__ float g_BU[(size_t)M_DIM * N_DIM];     // m-major
__device__ float g_Y0[(size_t)M_DIM * N_DIM];     // m-major, pre-relu refresh output
__device__ float g_X0buf[(size_t)M_DIM * N_DIM];  // m-major X ping-pong
__device__ float g_X1buf[(size_t)M_DIM * N_DIM];
__device__ float g_dX0[(size_t)M_DIM * N_DIM];    // residual ping-pong
__device__ float g_dX1[(size_t)M_DIM * N_DIM];
__device__ float g_part[8][(size_t)M_DIM * Q_DIM];
__device__ unsigned g_md[MAXIT];
__device__ unsigned g_barcnt;
__device__ float* g_fp1;
__device__ float* g_fp2;
__device__ int g_resid;

// ---------------- helpers ----------------
__device__ __forceinline__ uint32_t f2tf(float x) {
    uint32_t r;
    asm("cvt.rna.tf32.f32 %0, %1;" : "=r"(r) : "f"(x));
    return r;
}
__device__ __forceinline__ void mma8(float* d, const uint32_t* a, const uint32_t* b) {
    asm volatile(
        "mma.sync.aligned.m16n8k8.row.col.f32.tf32.tf32.f32 "
        "{%0,%1,%2,%3},{%4,%5,%6,%7},{%8,%9},{%0,%1,%2,%3};"
        : "+f"(d[0]), "+f"(d[1]), "+f"(d[2]), "+f"(d[3])
        : "r"(a[0]), "r"(a[1]), "r"(a[2]), "r"(a[3]), "r"(b[0]), "r"(b[1]));
}
__device__ __forceinline__ void split_st(float* hi, float* lo, int off, float4 v, int full) {
    float4 h;
    h.x = __uint_as_float(f2tf(v.x)); h.y = __uint_as_float(f2tf(v.y));
    h.z = __uint_as_float(f2tf(v.z)); h.w = __uint_as_float(f2tf(v.w));
    *(float4*)&hi[off] = h;
    if (full) {
        float4 l;
        l.x = __uint_as_float(f2tf(v.x - h.x)); l.y = __uint_as_float(f2tf(v.y - h.y));
        l.z = __uint_as_float(f2tf(v.z - h.z)); l.w = __uint_as_float(f2tf(v.w - h.w));
        *(float4*)&lo[off] = l;
    }
}

// ---------------- 64x128 GEMM tile: acc += Ab(64,k) * Bb(128,k)^T ----------------
// PRESPLIT: A operand already tf32 hi/lo (two gmem arrays); else raw fp32 split on the fly.
template <int PRESPLIT>
__device__ __forceinline__ void gemm_tile64(
    const float* __restrict__ Ahi, const float* __restrict__ Alo, int lda,
    const float* __restrict__ Bb, int ldb, int kdim, int full,
    float* __restrict__ sm, float acc[2][4][4])
{
    float* Ah = sm;
    float* Al = sm + SM_AL;
    float* Xh = sm + SM_XH;
    float* Xl = sm + SM_XL;
    int tid = threadIdx.x;
    int warp = tid >> 5, lane = tid & 31;
    int wm = warp >> 2, wn = warp & 3;
    int g = lane >> 2, c = lane & 3;
    int arow = tid & 63, aq = tid >> 6;     // 0..3
    int xrow = tid & 127, xq = tid >> 7;    // 0..1
    int sbA = arow * LDA + aq * 4;
    int sbX = xrow * LDA + xq * 8;

#pragma unroll
    for (int mi = 0; mi < 2; mi++)
#pragma unroll
        for (int ni = 0; ni < 4; ni++)
#pragma unroll
            for (int r = 0; r < 4; r++) acc[mi][ni][r] = 0.f;

    const float* aph = Ahi + (size_t)arow * lda + aq * 4;
    const float* apl = Alo + (size_t)arow * lda + aq * 4;
    const float* xp  = Bb + (size_t)xrow * ldb + xq * 8;

    float4 a_h = *(const float4*)aph;
    float4 a_l = make_float4(0.f, 0.f, 0.f, 0.f);
    if (PRESPLIT && full) a_l = *(const float4*)apl;
    float4 x0 = *(const float4*)xp, x1 = *(const float4*)(xp + 4);

    // stage 0 stores
    if (PRESPLIT) {
        *(float4*)&Ah[sbA] = a_h;
        if (full) *(float4*)&Al[sbA] = a_l;
    } else {
        split_st(Ah, Al, sbA, a_h, full);
    }
    split_st(Xh, Xl, sbX, x0, full);
    split_st(Xh, Xl, sbX + 4, x1, full);
    __syncthreads();

    int NST = kdim / KC;
    for (int s = 0; s < NST; s++) {
        int buf = s & 1;
        int ab = buf * 1280;
        int xb = buf * 2560;
        if (s + 1 < NST) {
            int kk = KC * (s + 1);
            a_h = *(const float4*)(aph + kk);
            if (PRESPLIT && full) a_l = *(const float4*)(apl + kk);
            x0 = *(const float4*)(xp + kk);
            x1 = *(const float4*)(xp + kk + 4);
        }
#pragma unroll
        for (int k8 = 0; k8 < KC; k8 += 8) {
            uint32_t ahf[2][4], bhf[4][2];
#pragma unroll
            for (int mi = 0; mi < 2; mi++) {
                int r0 = wm * 32 + mi * 16 + g;
                const float* p = &Ah[ab + r0 * LDA + k8 + c];
                ahf[mi][0] = __float_as_uint(p[0]);
                ahf[mi][1] = __float_as_uint(p[8 * LDA]);
                ahf[mi][2] = __float_as_uint(p[4]);
                ahf[mi][3] = __float_as_uint(p[8 * LDA + 4]);
            }
#pragma unroll
            for (int ni = 0; ni < 4; ni++) {
                int n0 = wn * 32 + ni * 8 + g;
                const float* p = &Xh[xb + n0 * LDA + k8 + c];
                bhf[ni][0] = __float_as_uint(p[0]);
                bhf[ni][1] = __float_as_uint(p[4]);
            }
            if (full) {
                uint32_t alf[2][4], blf[4][2];
#pragma unroll
                for (int mi = 0; mi < 2; mi++) {
                    int r0 = wm * 32 + mi * 16 + g;
                    const float* p = &Al[ab + r0 * LDA + k8 + c];
                    alf[mi][0] = __float_as_uint(p[0]);
                    alf[mi][1] = __float_as_uint(p[8 * LDA]);
                    alf[mi][2] = __float_as_uint(p[4]);
                    alf[mi][3] = __float_as_uint(p[8 * LDA + 4]);
                }
#pragma unroll
                for (int ni = 0; ni < 4; ni++) {
                    int n0 = wn * 32 + ni * 8 + g;
                    const float* p = &Xl[xb + n0 * LDA + k8 + c];
                    blf[ni][0] = __float_as_uint(p[0]);
                    blf[ni][1] = __float_as_uint(p[4]);
                }
#pragma unroll
                for (int mi = 0; mi < 2; mi++)
#pragma unroll
                    for (int ni = 0; ni < 4; ni++) {
                        mma8(acc[mi][ni], ahf[mi], bhf[ni]);
                        mma8(acc[mi][ni], ahf[mi], blf[ni]);
                        mma8(acc[mi][ni], alf[mi], bhf[ni]);
                    }
            } else {
#pragma unroll
                for (int mi = 0; mi < 2; mi++)
#pragma unroll
                    for (int ni = 0; ni < 4; ni++)
                        mma8(acc[mi][ni], ahf[mi], bhf[ni]);
            }
        }
        if (s + 1 < NST) {
            int nab = (buf ^ 1) * 1280 + sbA;
            int nxb = (buf ^ 1) * 2560 + sbX;
            if (PRESPLIT) {
                *(float4*)&Ah[nab] = a_h;
                if (full) *(float4*)&Al[nab] = a_l;
            } else {
                split_st(Ah, Al, nab, a_h, full);
            }
            split_st(Xh, Xl, nxb, x0, full);
            split_st(Xh, Xl, nxb + 4, x1, full);
        }
        __syncthreads();
    }
}

// ---------------- init ----------------
__global__ void init_kernel() {
    int t = threadIdx.x;
    for (int i = t; i < MAXIT; i += 256) g_md[i] = 0u;
    if (t == 0) { g_barcnt = 0u; g_resid = 0; }
}

// ---------------- projection of A + tf32 hi/lo presplit ----------------
__global__ __launch_bounds__(256) void project_kernel(const float* __restrict__ A) {
    __shared__ float warp_s[8];
    __shared__ float s_scale;
    int row = blockIdx.x;
    const float* ar = A + (size_t)row * N_DIM;
    float s = 0.f;
    for (int c = threadIdx.x; c < N_DIM; c += 256) s += fabsf(ar[c]);
#pragma unroll
    for (int o = 16; o; o >>= 1) s += __shfl_xor_sync(0xffffffffu, s, o);
    if ((threadIdx.x & 31) == 0) warp_s[threadIdx.x >> 5] = s;
    __syncthreads();
    if (threadIdx.x == 0) {
        float t = 0.f;
#pragma unroll
        for (int i = 0; i < 8; i++) t += warp_s[i];
        s_scale = fminf(1.f, KAPPA / fmaxf(t, 1e-12f));
    }
    __syncthreads();
    float sc = s_scale;
    float* oh = g_Ahi + (size_t)row * N_DIM;
    float* ol = g_Alo + (size_t)row * N_DIM;
    for (int c = threadIdx.x; c < N_DIM; c += 256) {
        float v = ar[c] * sc;
        float h = __uint_as_float(f2tf(v));
        oh[c] = h;
        ol[c] = __uint_as_float(f2tf(v - h));
    }
}

// ---------------- X0 (m,n) row-major == m-major: straight copy ----------------
__global__ void copyx0_kernel(const float* __restrict__ in) {
    size_t idx = (size_t)blockIdx.x * 256 + threadIdx.x;
    const float4* src = (const float4*)in;
    float4* dst = (float4*)g_X0buf;
    size_t tot = (size_t)M_DIM * N_DIM / 4;
    for (size_t i = idx; i < tot; i += (size_t)gridDim.x * 256) dst[i] = src[i];
}

// ---------------- BU[j][i] = sum_p B[i,p] U[j,p] via 3xTF32 tensor tile ----------------
__global__ __launch_bounds__(256, 2) void bu_kernel_t(const float* __restrict__ B,
                                                      const float* __restrict__ U) {
    extern __shared__ float sm[];
    int bid = blockIdx.x;
    int j0 = (bid & 15) * 128;
    int i0 = (bid >> 4) * 64;
    float acc[2][4][4];
    gemm_tile64<0>(B + (size_t)i0 * P_DIM, B + (size_t)i0 * P_DIM, P_DIM,
                   U + (size_t)j0 * P_DIM, P_DIM, P_DIM, 1, sm, acc);

    int warp = threadIdx.x >> 5, lane = threadIdx.x & 31;
    int wm = warp >> 2, wn = warp & 3;
    int g = lane >> 2, c = lane & 3;
#pragma unroll
    for (int mi = 0; mi < 2; mi++)
#pragma unroll
        for (int ni = 0; ni < 4; ni++)
#pragma unroll
            for (int r = 0; r < 4; r++) {
                int il = wm * 32 + mi * 16 + g + ((r >= 2) ? 8 : 0);
                int jl = wn * 32 + ni * 8 + 2 * c + (r & 1);
                g_BU[(size_t)(j0 + jl) * N_DIM + (i0 + il)] = acc[mi][ni][r];
            }
}

// ---------------- persistent hybrid Picard loop ----------------
__global__ __launch_bounds__(256, 2) void picard_kernel() {
    extern __shared__ float sm[];
    __shared__ float red[8];

    int tid = threadIdx.x;
    int warp = tid >> 5, lane = tid & 31;
    int wm = warp >> 2, wn = warp & 3;
    int g = lane >> 2, c = lane & 3;
    int bid = blockIdx.x;
    int j0 = (bid & 15) * 128;   // m tile
    int i0 = (bid >> 4) * 64;    // n tile

    float* Xb[2] = {g_X0buf, g_X1buf};
    float* Dd[2] = {g_dX0, g_dX1};

    int phase = 0;      // 0 = fast X, 1 = refresh, 2 = residual
    int curX = 0, curD = 0, base = 0;
    float* fin1 = g_X0buf;
    float* fin2 = g_X0buf;
    int finR = 0;

    for (int it = 0; it < MAXIT; it++) {
        int mode = phase;
        const float* __restrict__ in = (mode == 2) ? Dd[curD] : Xb[curX];
        float* __restrict__ out = (mode == 0) ? Xb[curX ^ 1]
                                 : (mode == 1) ? Dd[0] : Dd[curD ^ 1];
        int full = (mode == 1);
        const float* __restrict__ Xbase = Xb[(mode == 1) ? curX : base];

        float acc[2][4][4];
        gemm_tile64<1>(g_Ahi + (size_t)i0 * N_DIM, g_Alo + (size_t)i0 * N_DIM, N_DIM,
                       in + (size_t)j0 * N_DIM, N_DIM, N_DIM, full, sm, acc);

        // epilogue
        float maxd = 0.f;
#pragma unroll
        for (int mi = 0; mi < 2; mi++)
#pragma unroll
            for (int ni = 0; ni < 4; ni++)
#pragma unroll
                for (int r = 0; r < 4; r++) {
                    int il = wm * 32 + mi * 16 + g + ((r >= 2) ? 8 : 0);
                    int jl = wn * 32 + ni * 8 + 2 * c + (r & 1);
                    size_t adr = (size_t)(j0 + jl) * N_DIM + (i0 + il);
                    float a = acc[mi][ni][r];
                    if (mode == 0) {
                        float v = fmaxf(a + g_BU[adr], 0.f);
                        maxd = fmaxf(maxd, fabsf(v - in[adr]));
                        out[adr] = v;
                    } else if (mode == 1) {
                        float t = a + g_BU[adr];
                        g_Y0[adr] = t;
                        float v = fmaxf(t, 0.f);
                        float d = v - in[adr];      // Xbase == in
                        maxd = fmaxf(maxd, fabsf(d));
                        out[adr] = d;
                    } else {
                        float v = fmaxf(a + g_Y0[adr], 0.f);
                        float d = v - Xbase[adr];
                        maxd = fmaxf(maxd, fabsf(d - in[adr]));
                        out[adr] = d;
                    }
                }
#pragma unroll
        for (int o = 16; o; o >>= 1) maxd = fmaxf(maxd, __shfl_xor_sync(0xffffffffu, maxd, o));
        if (lane == 0) red[warp] = maxd;
        __syncthreads();
        if (tid == 0) {
            float m = red[0];
#pragma unroll
            for (int i2 = 1; i2 < 8; i2++) m = fmaxf(m, red[i2]);
            atomicMax(&g_md[it], __float_as_uint(m));
        }
        __syncthreads();

        // software grid barrier (256 blocks, 2/SM guaranteed by launch bounds + smem)
        if (tid == 0) {
            __threadfence();
            atomicAdd(&g_barcnt, 1u);
            unsigned target = (unsigned)(it + 1) * NBLK;
            while (atomicAdd(&g_barcnt, 0u) < target) {}
            __threadfence();
        }
        __syncthreads();

        float md = __uint_as_float(g_md[it]);
        fin1 = (mode == 0) ? out : (float*)Xbase;
        fin2 = out;
        finR = (mode >= 1);
        if (md <= TOL) break;

        if (mode == 0) {
            curX ^= 1;
            if (md <= SWITCH_MD) phase = 1;
        } else if (mode == 1) {
            base = curX;
            phase = 2;
            curD = 0;
        } else {
            curD ^= 1;
        }
    }

    if (bid == 0 && tid == 0) {
        g_fp1 = fin1;
        g_fp2 = fin2;
        g_resid = finR;
    }
}

// ---------------- final: k-split x8 partials; X = fp1 (+ fp2 if resid) ----------------
__global__ __launch_bounds__(256) void final_part_kernel(const float* __restrict__ Cm,
                                                         const float* __restrict__ Dm,
                                                         const float* __restrict__ U) {
    const float* __restrict__ F1 = g_fp1;
    const float* __restrict__ F2 = g_fp2;
    int resid = g_resid;
    __shared__ float As[16][132];
    __shared__ float Bs[16][132];
    int j0 = blockIdx.x * 128;
    int part = blockIdx.y;      // 0..7
    int tid = threadIdx.x;
    int lk = tid & 15, lb = tid >> 4;
    int tx = tid & 15, ty = tid >> 4;
    float acc[8][8] = {};

    int n_lo = part * (N_DIM / 8), n_hi = n_lo + N_DIM / 8;
    for (int kk = n_lo; kk < n_hi; kk += 16) {
        __syncthreads();
#pragma unroll
        for (int r = 0; r < 8; r++) {
            As[lk][lb + 16 * r] = Cm[(size_t)(lb + 16 * r) * N_DIM + kk + lk];
            size_t off = (size_t)(j0 + lb + 16 * r) * N_DIM + kk + lk;
            float xv = F1[off];
            if (resid) xv += F2[off];
            Bs[lk][lb + 16 * r] = xv;
        }
        __syncthreads();
#pragma unroll
        for (int k = 0; k < 16; k++) {
            float a[8], b[8];
#pragma unroll
            for (int i = 0; i < 8; i++) a[i] = As[k][ty * 8 + i];
#pragma unroll
            for (int j = 0; j < 8; j++) b[j] = Bs[k][tx * 8 + j];
#pragma unroll
            for (int i = 0; i < 8; i++)
#pragma unroll
                for (int j = 0; j < 8; j++) acc[i][j] = fmaf(a[i], b[j], acc[i][j]);
        }
    }
    int p_lo = part * (P_DIM / 8), p_hi = p_lo + P_DIM / 8;
    for (int kk = p_lo; kk < p_hi; kk += 16) {
        __syncthreads();
#pragma unroll
        for (int r = 0; r < 8; r++) {
            As[lk][lb + 16 * r] = Dm[(size_t)(lb + 16 * r) * P_DIM + kk + lk];
            Bs[lk][lb + 16 * r] = U[(size_t)(j0 + lb + 16 * r) * P_DIM + kk + lk];
        }
        __syncthreads();
#pragma unroll
        for (int k = 0; k < 16; k++) {
            float a[8], b[8];
#pragma unroll
            for (int i = 0; i < 8; i++) a[i] = As[k][ty * 8 + i];
#pragma unroll
            for (int j = 0; j < 8; j++) b[j] = Bs[k][tx * 8 + j];
#pragma unroll
            for (int i = 0; i < 8; i++)
#pragma unroll
                for (int j = 0; j < 8; j++) acc[i][j] = fmaf(a[i], b[j], acc[i][j]);
        }
    }
    float* outp = g_part[part];
#pragma unroll
    for (int j = 0; j < 8; j++) {
        size_t off = (size_t)(j0 + tx * 8 + j) * Q_DIM + ty * 8;
        *(float4*)(outp + off)     = make_float4(acc[0][j], acc[1][j], acc[2][j], acc[3][j]);
        *(float4*)(outp + off + 4) = make_float4(acc[4][j], acc[5][j], acc[6][j], acc[7][j]);
    }
}

__global__ void final_reduce_kernel(float* __restrict__ outp) {
    size_t idx = (size_t)blockIdx.x * 256 + threadIdx.x;
    size_t tot = (size_t)M_DIM * Q_DIM / 4;
    float4* o = (float4*)outp;
    for (size_t i = idx; i < tot; i += (size_t)gridDim.x * 256) {
        float4 s = ((const float4*)g_part[0])[i];
#pragma unroll
        for (int p = 1; p < 8; p++) {
            float4 v = ((const float4*)g_part[p])[i];
            s.x += v.x; s.y += v.y; s.z += v.z; s.w += v.w;
        }
        o[i] = s;
    }
}

// ---------------- launcher ----------------
extern "C" void kernel_launch(void* const* d_in, const int* in_sizes, int n_in,
                              void* d_out, int out_size) {
    (void)in_sizes; (void)n_in; (void)out_size;
    const float* U  = (const float*)d_in[0];
    const float* X0 = (const float*)d_in[1];
    const float* A  = (const float*)d_in[2];
    const float* B  = (const float*)d_in[3];
    const float* Cm = (const float*)d_in[4];
    const float* Dm = (const float*)d_in[5];
    float* outp = (float*)d_out;

    cudaFuncSetAttribute(picard_kernel, cudaFuncAttributeMaxDynamicSharedMemorySize, DSMEM_BYTES);
    cudaFuncSetAttribute(bu_kernel_t, cudaFuncAttributeMaxDynamicSharedMemorySize, DSMEM_BYTES);

    init_kernel<<<1, 256>>>();
    project_kernel<<<N_DIM, 256>>>(A);
    copyx0_kernel<<<512, 256>>>(X0);
    bu_kernel_t<<<NBLK, 256, DSMEM_BYTES>>>(B, U);
    picard_kernel<<<NBLK, 256, DSMEM_BYTES>>>();
    final_part_kernel<<<dim3(M_DIM / 128, 8), 256>>>(Cm, Dm, U);
    final_reduce_kernel<<<64, 256>>>(outp);
}

// round 8
// speedup vs baseline: 1.1892x; 1.1892x over previous
#include <cuda_runtime.h>
#include <cstdint>

#define N_DIM 1024
#define M_DIM 2048
#define P_DIM 512
#define Q_DIM 128
#define KAPPA 0.99f
#define TOL   3e-6f
#define SWITCH_MD 1e-3f
#define MAXIT 300
#define NBLK  128

#define KC   16
#define LDA  24                  // row stride (floats): conflict-free LDS.64 half-phases
#define SM_BUF 3072              // 128 * LDA floats per buffer
// layout (floats): Ah[2][3072] @0, Al @6144, Xh @12288, Xl @18432
#define DSMEM_BYTES (24576 * 4)

// ---------------- device state ----------------
__device__ float g_Ahi[(size_t)N_DIM * N_DIM];
__device__ float g_Alo[(size_t)N_DIM * N_DIM];
__device__ float g_BU[(size_t)M_DIM * N_DIM];     // m-major
__device__ float g_Y0[(size_t)M_DIM * N_DIM];     // m-major, pre-relu refresh output
__device__ float g_X0buf[(size_t)M_DIM * N_DIM];  // m-major X ping-pong
__device__ float g_X1buf[(size_t)M_DIM * N_DIM];
__device__ float g_dX0[(size_t)M_DIM * N_DIM];    // residual ping-pong
__device__ float g_dX1[(size_t)M_DIM * N_DIM];
__device__ float g_part[8][(size_t)M_DIM * Q_DIM];
__device__ unsigned g_md[MAXIT];
__device__ unsigned g_barcnt;
__device__ float* g_fp1;
__device__ float* g_fp2;
__device__ int g_resid;

// ---------------- helpers ----------------
__device__ __forceinline__ uint32_t f2tf(float x) {
    uint32_t r;
    asm("cvt.rna.tf32.f32 %0, %1;" : "=r"(r) : "f"(x));
    return r;
}
__device__ __forceinline__ float tf(float x) { return __uint_as_float(f2tf(x)); }

__device__ __forceinline__ void mma8(float* d, const uint32_t* a, const uint32_t* b) {
    asm volatile(
        "mma.sync.aligned.m16n8k8.row.col.f32.tf32.tf32.f32 "
        "{%0,%1,%2,%3},{%4,%5,%6,%7},{%8,%9},{%0,%1,%2,%3};"
        : "+f"(d[0]), "+f"(d[1]), "+f"(d[2]), "+f"(d[3])
        : "r"(a[0]), "r"(a[1]), "r"(a[2]), "r"(a[3]), "r"(b[0]), "r"(b[1]));
}

// interleaved store: k-block position 2*(j&3)+(j>>2); v0 = j0..3, v1 = j4..7
__device__ __forceinline__ void perm_st(float* dst, int off, float4 v0, float4 v1) {
    *(float4*)&dst[off]     = make_float4(v0.x, v1.x, v0.y, v1.y);
    *(float4*)&dst[off + 4] = make_float4(v0.z, v1.z, v0.w, v1.w);
}
__device__ __forceinline__ void perm_split(float* hi, float* lo, int off,
                                           float4 v0, float4 v1, int full) {
    float4 h0 = make_float4(tf(v0.x), tf(v0.y), tf(v0.z), tf(v0.w));
    float4 h1 = make_float4(tf(v1.x), tf(v1.y), tf(v1.z), tf(v1.w));
    perm_st(hi, off, h0, h1);
    if (full) {
        float4 l0 = make_float4(tf(v0.x - h0.x), tf(v0.y - h0.y),
                                tf(v0.z - h0.z), tf(v0.w - h0.w));
        float4 l1 = make_float4(tf(v1.x - h1.x), tf(v1.y - h1.y),
                                tf(v1.z - h1.z), tf(v1.w - h1.w));
        perm_st(lo, off, l0, l1);
    }
}

// ---------------- 128x128 GEMM tile: acc += Ab(128,k) * Bb(128,k)^T ----------------
template <int PRESPLIT>
__device__ __forceinline__ void gemm_tile(
    const float* __restrict__ Ahi, const float* __restrict__ Alo, int lda,
    const float* __restrict__ Bb, int ldb, int kdim, int full,
    float* __restrict__ sm, float acc[4][4][4])
{
    float* Ah = sm;
    float* Al = sm + 6144;
    float* Xh = sm + 12288;
    float* Xl = sm + 18432;
    int tid = threadIdx.x;
    int warp = tid >> 5, lane = tid & 31;
    int wm = warp >> 2, wn = warp & 3;
    int g = lane >> 2, c = lane & 3;
    int lrow = tid & 127, lh = tid >> 7;
    int sbase = lrow * LDA + lh * 8;

#pragma unroll
    for (int mi = 0; mi < 4; mi++)
#pragma unroll
        for (int ni = 0; ni < 4; ni++)
#pragma unroll
            for (int r = 0; r < 4; r++) acc[mi][ni][r] = 0.f;

    const float* aph = Ahi + (size_t)lrow * lda + lh * 8;
    const float* apl = Alo + (size_t)lrow * lda + lh * 8;
    const float* xp  = Bb  + (size_t)lrow * ldb + lh * 8;

    float4 a0 = *(const float4*)aph, a1 = *(const float4*)(aph + 4);
    float4 al0 = make_float4(0, 0, 0, 0), al1 = make_float4(0, 0, 0, 0);
    if (PRESPLIT && full) { al0 = *(const float4*)apl; al1 = *(const float4*)(apl + 4); }
    float4 x0 = *(const float4*)xp, x1 = *(const float4*)(xp + 4);

    if (PRESPLIT) {
        perm_st(Ah, sbase, a0, a1);
        if (full) perm_st(Al, sbase, al0, al1);
    } else {
        perm_split(Ah, Al, sbase, a0, a1, full);
    }
    perm_split(Xh, Xl, sbase, x0, x1, full);
    __syncthreads();

    int NST = kdim / KC;
    for (int s = 0; s < NST; s++) {
        int buf = s & 1;
        int ab = buf * SM_BUF;
        if (s + 1 < NST) {
            int kk = KC * (s + 1);
            a0 = *(const float4*)(aph + kk); a1 = *(const float4*)(aph + kk + 4);
            if (PRESPLIT && full) {
                al0 = *(const float4*)(apl + kk); al1 = *(const float4*)(apl + kk + 4);
            }
            x0 = *(const float4*)(xp + kk); x1 = *(const float4*)(xp + kk + 4);
        }
#pragma unroll
        for (int k8 = 0; k8 < KC; k8 += 8) {
            uint32_t ahf[4][4], bhf[4][2];
#pragma unroll
            for (int mi = 0; mi < 4; mi++) {
                int r0 = wm * 64 + mi * 16 + g;
                float2 t0 = *(const float2*)&Ah[ab + r0 * LDA + k8 + 2 * c];
                float2 t1 = *(const float2*)&Ah[ab + (r0 + 8) * LDA + k8 + 2 * c];
                ahf[mi][0] = __float_as_uint(t0.x);
                ahf[mi][1] = __float_as_uint(t1.x);
                ahf[mi][2] = __float_as_uint(t0.y);
                ahf[mi][3] = __float_as_uint(t1.y);
            }
#pragma unroll
            for (int ni = 0; ni < 4; ni++) {
                int n0 = wn * 32 + ni * 8 + g;
                float2 t = *(const float2*)&Xh[ab + n0 * LDA + k8 + 2 * c];
                bhf[ni][0] = __float_as_uint(t.x);
                bhf[ni][1] = __float_as_uint(t.y);
            }
            if (full) {
                uint32_t alf[4][4], blf[4][2];
#pragma unroll
                for (int mi = 0; mi < 4; mi++) {
                    int r0 = wm * 64 + mi * 16 + g;
                    float2 t0 = *(const float2*)&Al[ab + r0 * LDA + k8 + 2 * c];
                    float2 t1 = *(const float2*)&Al[ab + (r0 + 8) * LDA + k8 + 2 * c];
                    alf[mi][0] = __float_as_uint(t0.x);
                    alf[mi][1] = __float_as_uint(t1.x);
                    alf[mi][2] = __float_as_uint(t0.y);
                    alf[mi][3] = __float_as_uint(t1.y);
                }
#pragma unroll
                for (int ni = 0; ni < 4; ni++) {
                    int n0 = wn * 32 + ni * 8 + g;
                    float2 t = *(const float2*)&Xl[ab + n0 * LDA + k8 + 2 * c];
                    blf[ni][0] = __float_as_uint(t.x);
                    blf[ni][1] = __float_as_uint(t.y);
                }
#pragma unroll
                for (int mi = 0; mi < 4; mi++)
#pragma unroll
                    for (int ni = 0; ni < 4; ni++) {
                        mma8(acc[mi][ni], ahf[mi], bhf[ni]);
                        mma8(acc[mi][ni], ahf[mi], blf[ni]);
                        mma8(acc[mi][ni], alf[mi], bhf[ni]);
                    }
            } else {
#pragma unroll
                for (int mi = 0; mi < 4; mi++)
#pragma unroll
                    for (int ni = 0; ni < 4; ni++)
                        mma8(acc[mi][ni], ahf[mi], bhf[ni]);
            }
        }
        if (s + 1 < NST) {
            int nb = (buf ^ 1) * SM_BUF + sbase;
            if (PRESPLIT) {
                perm_st(Ah, nb, a0, a1);
                if (full) perm_st(Al, nb, al0, al1);
            } else {
                perm_split(Ah, Al, nb, a0, a1, full);
            }
            perm_split(Xh, Xl, nb, x0, x1, full);
        }
        __syncthreads();
    }
}

// ---------------- init ----------------
__global__ void init_kernel() {
    int t = threadIdx.x;
    for (int i = t; i < MAXIT; i += 256) g_md[i] = 0u;
    if (t == 0) { g_barcnt = 0u; g_resid = 0; }
}

// ---------------- projection of A + tf32 hi/lo presplit ----------------
__global__ __launch_bounds__(256) void project_kernel(const float* __restrict__ A) {
    __shared__ float warp_s[8];
    __shared__ float s_scale;
    int row = blockIdx.x;
    const float* ar = A + (size_t)row * N_DIM;
    float s = 0.f;
    for (int c = threadIdx.x; c < N_DIM; c += 256) s += fabsf(ar[c]);
#pragma unroll
    for (int o = 16; o; o >>= 1) s += __shfl_xor_sync(0xffffffffu, s, o);
    if ((threadIdx.x & 31) == 0) warp_s[threadIdx.x >> 5] = s;
    __syncthreads();
    if (threadIdx.x == 0) {
        float t = 0.f;
#pragma unroll
        for (int i = 0; i < 8; i++) t += warp_s[i];
        s_scale = fminf(1.f, KAPPA / fmaxf(t, 1e-12f));
    }
    __syncthreads();
    float sc = s_scale;
    float* oh = g_Ahi + (size_t)row * N_DIM;
    float* ol = g_Alo + (size_t)row * N_DIM;
    for (int c = threadIdx.x; c < N_DIM; c += 256) {
        float v = ar[c] * sc;
        float h = tf(v);
        oh[c] = h;
        ol[c] = tf(v - h);
    }
}

// ---------------- X0 (m,n) row-major == m-major: straight copy ----------------
__global__ void copyx0_kernel(const float* __restrict__ in) {
    size_t idx = (size_t)blockIdx.x * 256 + threadIdx.x;
    const float4* src = (const float4*)in;
    float4* dst = (float4*)g_X0buf;
    size_t tot = (size_t)M_DIM * N_DIM / 4;
    for (size_t i = idx; i < tot; i += (size_t)gridDim.x * 256) dst[i] = src[i];
}

// ---------------- BU[j][i] = sum_p B[i,p] U[j,p] via 3xTF32 tensor tile ----------------
__global__ __launch_bounds__(256, 1) void bu_kernel_t(const float* __restrict__ B,
                                                      const float* __restrict__ U) {
    extern __shared__ float sm[];
    int bid = blockIdx.x;
    int j0 = (bid & 15) * 128;
    int i0 = (bid >> 4) * 128;
    float acc[4][4][4];
    gemm_tile<0>(B + (size_t)i0 * P_DIM, B + (size_t)i0 * P_DIM, P_DIM,
                 U + (size_t)j0 * P_DIM, P_DIM, P_DIM, 1, sm, acc);

    int warp = threadIdx.x >> 5, lane = threadIdx.x & 31;
    int wm = warp >> 2, wn = warp & 3;
    int g = lane >> 2, c = lane & 3;
#pragma unroll
    for (int mi = 0; mi < 4; mi++)
#pragma unroll
        for (int ni = 0; ni < 4; ni++)
#pragma unroll
            for (int r = 0; r < 4; r++) {
                int il = wm * 64 + mi * 16 + g + ((r >= 2) ? 8 : 0);
                int jl = wn * 32 + ni * 8 + 2 * c + (r & 1);
                g_BU[(size_t)(j0 + jl) * N_DIM + (i0 + il)] = acc[mi][ni][r];
            }
}

// ---------------- persistent hybrid Picard loop ----------------
__global__ __launch_bounds__(256, 1) void picard_kernel() {
    extern __shared__ float sm[];
    __shared__ float red[8];

    int tid = threadIdx.x;
    int warp = tid >> 5, lane = tid & 31;
    int wm = warp >> 2, wn = warp & 3;
    int g = lane >> 2, c = lane & 3;
    int bid = blockIdx.x;
    int j0 = (bid & 15) * 128;   // m tile
    int i0 = (bid >> 4) * 128;   // n tile

    float* Xb[2] = {g_X0buf, g_X1buf};
    float* Dd[2] = {g_dX0, g_dX1};

    int phase = 0;      // 0 = fast X, 1 = refresh, 2 = residual
    int curX = 0, curD = 0, base = 0;
    float* fin1 = g_X0buf;
    float* fin2 = g_X0buf;
    int finR = 0;

    for (int it = 0; it < MAXIT; it++) {
        int mode = phase;
        const float* __restrict__ in = (mode == 2) ? Dd[curD] : Xb[curX];
        float* __restrict__ out = (mode == 0) ? Xb[curX ^ 1]
                                 : (mode == 1) ? Dd[0] : Dd[curD ^ 1];
        int full = (mode == 1);
        const float* __restrict__ Xbase = Xb[(mode == 1) ? curX : base];

        float acc[4][4][4];
        gemm_tile<1>(g_Ahi + (size_t)i0 * N_DIM, g_Alo + (size_t)i0 * N_DIM, N_DIM,
                     in + (size_t)j0 * N_DIM, N_DIM, N_DIM, full, sm, acc);

        // epilogue
        float maxd = 0.f;
#pragma unroll
        for (int mi = 0; mi < 4; mi++)
#pragma unroll
            for (int ni = 0; ni < 4; ni++)
#pragma unroll
                for (int r = 0; r < 4; r++) {
                    int il = wm * 64 + mi * 16 + g + ((r >= 2) ? 8 : 0);
                    int jl = wn * 32 + ni * 8 + 2 * c + (r & 1);
                    size_t adr = (size_t)(j0 + jl) * N_DIM + (i0 + il);
                    float a = acc[mi][ni][r];
                    if (mode == 0) {
                        float v = fmaxf(a + g_BU[adr], 0.f);
                        maxd = fmaxf(maxd, fabsf(v - in[adr]));
                        out[adr] = v;
                    } else if (mode == 1) {
                        float t = a + g_BU[adr];
                        g_Y0[adr] = t;
                        float v = fmaxf(t, 0.f);
                        float d = v - in[adr];      // Xbase == in
                        maxd = fmaxf(maxd, fabsf(d));
                        out[adr] = d;
                    } else {
                        float v = fmaxf(a + g_Y0[adr], 0.f);
                        float d = v - Xbase[adr];
                        maxd = fmaxf(maxd, fabsf(d - in[adr]));
                        out[adr] = d;
                    }
                }
#pragma unroll
        for (int o = 16; o; o >>= 1) maxd = fmaxf(maxd, __shfl_xor_sync(0xffffffffu, maxd, o));
        if (lane == 0) red[warp] = maxd;
        __syncthreads();
        if (tid == 0) {
            float m = red[0];
#pragma unroll
            for (int i2 = 1; i2 < 8; i2++) m = fmaxf(m, red[i2]);
            atomicMax(&g_md[it], __float_as_uint(m));
        }
        __syncthreads();

        // software grid barrier (128 blocks co-resident on 148 SMs)
        if (tid == 0) {
            __threadfence();
            atomicAdd(&g_barcnt, 1u);
            unsigned target = (unsigned)(it + 1) * NBLK;
            while (atomicAdd(&g_barcnt, 0u) < target) {}
            __threadfence();
        }
        __syncthreads();

        float md = __uint_as_float(g_md[it]);
        fin1 = (mode == 0) ? out : (float*)Xbase;
        fin2 = out;
        finR = (mode >= 1);
        if (md <= TOL) break;

        if (mode == 0) {
            curX ^= 1;
            if (md <= SWITCH_MD) phase = 1;
        } else if (mode == 1) {
            base = curX;
            phase = 2;
            curD = 0;
        } else {
            curD ^= 1;
        }
    }

    if (bid == 0 && tid == 0) {
        g_fp1 = fin1;
        g_fp2 = fin2;
        g_resid = finR;
    }
}

// ---------------- final: k-split x8 partials; X = fp1 (+ fp2 if resid) ----------------
__global__ __launch_bounds__(256) void final_part_kernel(const float* __restrict__ Cm,
                                                         const float* __restrict__ Dm,
                                                         const float* __restrict__ U) {
    const float* __restrict__ F1 = g_fp1;
    const float* __restrict__ F2 = g_fp2;
    int resid = g_resid;
    __shared__ float As[16][132];
    __shared__ float Bs[16][132];
    int j0 = blockIdx.x * 128;
    int part = blockIdx.y;      // 0..7
    int tid = threadIdx.x;
    int lk = tid & 15, lb = tid >> 4;
    int tx = tid & 15, ty = tid >> 4;
    float acc[8][8] = {};

    int n_lo = part * (N_DIM / 8), n_hi = n_lo + N_DIM / 8;
    for (int kk = n_lo; kk < n_hi; kk += 16) {
        __syncthreads();
#pragma unroll
        for (int r = 0; r < 8; r++) {
            As[lk][lb + 16 * r] = Cm[(size_t)(lb + 16 * r) * N_DIM + kk + lk];
            size_t off = (size_t)(j0 + lb + 16 * r) * N_DIM + kk + lk;
            float xv = F1[off];
            if (resid) xv += F2[off];
            Bs[lk][lb + 16 * r] = xv;
        }
        __syncthreads();
#pragma unroll
        for (int k = 0; k < 16; k++) {
            float a[8], b[8];
#pragma unroll
            for (int i = 0; i < 8; i++) a[i] = As[k][ty * 8 + i];
#pragma unroll
            for (int j = 0; j < 8; j++) b[j] = Bs[k][tx * 8 + j];
#pragma unroll
            for (int i = 0; i < 8; i++)
#pragma unroll
                for (int j = 0; j < 8; j++) acc[i][j] = fmaf(a[i], b[j], acc[i][j]);
        }
    }
    int p_lo = part * (P_DIM / 8), p_hi = p_lo + P_DIM / 8;
    for (int kk = p_lo; kk < p_hi; kk += 16) {
        __syncthreads();
#pragma unroll
        for (int r = 0; r < 8; r++) {
            As[lk][lb + 16 * r] = Dm[(size_t)(lb + 16 * r) * P_DIM + kk + lk];
            Bs[lk][lb + 16 * r] = U[(size_t)(j0 + lb + 16 * r) * P_DIM + kk + lk];
        }
        __syncthreads();
#pragma unroll
        for (int k = 0; k < 16; k++) {
            float a[8], b[8];
#pragma unroll
            for (int i = 0; i < 8; i++) a[i] = As[k][ty * 8 + i];
#pragma unroll
            for (int j = 0; j < 8; j++) b[j] = Bs[k][tx * 8 + j];
#pragma unroll
            for (int i = 0; i < 8; i++)
#pragma unroll
                for (int j = 0; j < 8; j++) acc[i][j] = fmaf(a[i], b[j], acc[i][j]);
        }
    }
    float* outp = g_part[part];
#pragma unroll
    for (int j = 0; j < 8; j++) {
        size_t off = (size_t)(j0 + tx * 8 + j) * Q_DIM + ty * 8;
        *(float4*)(outp + off)     = make_float4(acc[0][j], acc[1][j], acc[2][j], acc[3][j]);
        *(float4*)(outp + off + 4) = make_float4(acc[4][j], acc[5][j], acc[6][j], acc[7][j]);
    }
}

__global__ void final_reduce_kernel(float* __restrict__ outp) {
    size_t idx = (size_t)blockIdx.x * 256 + threadIdx.x;
    size_t tot = (size_t)M_DIM * Q_DIM / 4;
    float4* o = (float4*)outp;
    for (size_t i = idx; i < tot; i += (size_t)gridDim.x * 256) {
        float4 s = ((const float4*)g_part[0])[i];
#pragma unroll
        for (int p = 1; p < 8; p++) {
            float4 v = ((const float4*)g_part[p])[i];
            s.x += v.x; s.y += v.y; s.z += v.z; s.w += v.w;
        }
        o[i] = s;
    }
}

// ---------------- launcher ----------------
extern "C" void kernel_launch(void* const* d_in, const int* in_sizes, int n_in,
                              void* d_out, int out_size) {
    (void)in_sizes; (void)n_in; (void)out_size;
    const float* U  = (const float*)d_in[0];
    const float* X0 = (const float*)d_in[1];
    const float* A  = (const float*)d_in[2];
    const float* B  = (const float*)d_in[3];
    const float* Cm = (const float*)d_in[4];
    const float* Dm = (const float*)d_in[5];
    float* outp = (float*)d_out;

    cudaFuncSetAttribute(picard_kernel, cudaFuncAttributeMaxDynamicSharedMemorySize, DSMEM_BYTES);
    cudaFuncSetAttribute(bu_kernel_t, cudaFuncAttributeMaxDynamicSharedMemorySize, DSMEM_BYTES);

    init_kernel<<<1, 256>>>();
    project_kernel<<<N_DIM, 256>>>(A);
    copyx0_kernel<<<512, 256>>>(X0);
    bu_kernel_t<<<NBLK, 256, DSMEM_BYTES>>>(B, U);
    picard_kernel<<<NBLK, 256, DSMEM_BYTES>>>();
    final_part_kernel<<<dim3(M_DIM / 128, 8), 256>>>(Cm, Dm, U);
    final_reduce_kernel<<<64, 256>>>(outp);
}

// round 9
// speedup vs baseline: 1.4108x; 1.1864x over previous
#include <cuda_runtime.h>
#include <cstdint>

#define N_DIM 1024
#define M_DIM 2048
#define P_DIM 512
#define Q_DIM 128
#define KAPPA 0.99f
#define TOL   3e-6f
#define SWITCH_MD 1e-3f
#define MAXIT 300
#define NBLK  128

#define KC   32
#define LDA  40                  // row stride (floats): LDS.64 fragment phases conflict-free
#define SM_BUF 5120              // 128 * LDA floats per buffer
// layout (floats): Ah[2] @0, Al[2] @10240, Xh[2] @20480, Xl[2] @30720
#define DSMEM_BYTES (40960 * 4)

// ---------------- device state ----------------
__device__ float g_Ahi[(size_t)N_DIM * N_DIM];
__device__ float g_Alo[(size_t)N_DIM * N_DIM];
__device__ float g_BU[(size_t)M_DIM * N_DIM];     // m-major
__device__ float g_Y0[(size_t)M_DIM * N_DIM];     // m-major, pre-relu refresh output
__device__ float g_X0buf[(size_t)M_DIM * N_DIM];  // m-major X ping-pong
__device__ float g_X1buf[(size_t)M_DIM * N_DIM];
__device__ float g_dX0[(size_t)M_DIM * N_DIM];    // residual ping-pong
__device__ float g_dX1[(size_t)M_DIM * N_DIM];
__device__ float g_part[8][(size_t)M_DIM * Q_DIM];
__device__ unsigned g_md[MAXIT];
__device__ unsigned g_barcnt;
__device__ unsigned g_x0nz;
__device__ float* g_fp1;
__device__ float* g_fp2;
__device__ int g_resid;

// ---------------- helpers ----------------
__device__ __forceinline__ uint32_t f2tf(float x) {
    uint32_t r;
    asm("cvt.rna.tf32.f32 %0, %1;" : "=r"(r) : "f"(x));
    return r;
}
__device__ __forceinline__ float tf(float x) { return __uint_as_float(f2tf(x)); }

__device__ __forceinline__ void mma8(float* d, const uint32_t* a, const uint32_t* b) {
    asm volatile(
        "mma.sync.aligned.m16n8k8.row.col.f32.tf32.tf32.f32 "
        "{%0,%1,%2,%3},{%4,%5,%6,%7},{%8,%9},{%0,%1,%2,%3};"
        : "+f"(d[0]), "+f"(d[1]), "+f"(d[2]), "+f"(d[3])
        : "r"(a[0]), "r"(a[1]), "r"(a[2]), "r"(a[3]), "r"(b[0]), "r"(b[1]));
}

// interleaved store: within 8-col block, col j -> 2*(j&3)+(j>>2)
__device__ __forceinline__ void perm_st(float* dst, int off, float4 v0, float4 v1) {
    *(float4*)&dst[off]     = make_float4(v0.x, v1.x, v0.y, v1.y);
    *(float4*)&dst[off + 4] = make_float4(v0.z, v1.z, v0.w, v1.w);
}
__device__ __forceinline__ void perm_split(float* hi, float* lo, int off,
                                           float4 v0, float4 v1, int full) {
    float4 h0 = make_float4(tf(v0.x), tf(v0.y), tf(v0.z), tf(v0.w));
    float4 h1 = make_float4(tf(v1.x), tf(v1.y), tf(v1.z), tf(v1.w));
    perm_st(hi, off, h0, h1);
    if (full) {
        float4 l0 = make_float4(tf(v0.x - h0.x), tf(v0.y - h0.y),
                                tf(v0.z - h0.z), tf(v0.w - h0.w));
        float4 l1 = make_float4(tf(v1.x - h1.x), tf(v1.y - h1.y),
                                tf(v1.z - h1.z), tf(v1.w - h1.w));
        perm_st(lo, off, l0, l1);
    }
}

// ---------------- 128x128 GEMM tile: acc += Ab(128,k) * Bb(128,k)^T, KC=32 ----------------
template <int PRESPLIT>
__device__ __forceinline__ void gemm_tile(
    const float* __restrict__ Ahi, const float* __restrict__ Alo, int lda,
    const float* __restrict__ Bb, int ldb, int kdim, int full,
    float* __restrict__ sm, float acc[4][4][4])
{
    float* Ah = sm;
    float* Al = sm + 10240;
    float* Xh = sm + 20480;
    float* Xl = sm + 30720;
    int tid = threadIdx.x;
    int warp = tid >> 5, lane = tid & 31;
    int wm = warp >> 2, wn = warp & 3;
    int g = lane >> 2, c = lane & 3;
    int lrow = tid & 127, lh = tid >> 7;       // col half: lh*16
    int sbase = lrow * LDA + lh * 16;

    const float* aph = Ahi + (size_t)lrow * lda + lh * 16;
    const float* apl = Alo + (size_t)lrow * lda + lh * 16;
    const float* xp  = Bb  + (size_t)lrow * ldb + lh * 16;

    float4 a[4], al[4], x[4];
#pragma unroll
    for (int i = 0; i < 4; i++) a[i] = *(const float4*)(aph + 4 * i);
    if (PRESPLIT && full)
#pragma unroll
        for (int i = 0; i < 4; i++) al[i] = *(const float4*)(apl + 4 * i);
#pragma unroll
    for (int i = 0; i < 4; i++) x[i] = *(const float4*)(xp + 4 * i);

    if (PRESPLIT) {
        perm_st(Ah, sbase, a[0], a[1]);
        perm_st(Ah, sbase + 8, a[2], a[3]);
        if (full) {
            perm_st(Al, sbase, al[0], al[1]);
            perm_st(Al, sbase + 8, al[2], al[3]);
        }
    } else {
        perm_split(Ah, Al, sbase, a[0], a[1], full);
        perm_split(Ah, Al, sbase + 8, a[2], a[3], full);
    }
    perm_split(Xh, Xl, sbase, x[0], x[1], full);
    perm_split(Xh, Xl, sbase + 8, x[2], x[3], full);
    __syncthreads();

    int NST = kdim / KC;
    for (int s = 0; s < NST; s++) {
        int buf = s & 1;
        int ab = buf * SM_BUF;
        if (s + 1 < NST) {
            int kk = KC * (s + 1);
#pragma unroll
            for (int i = 0; i < 4; i++) a[i] = *(const float4*)(aph + kk + 4 * i);
            if (PRESPLIT && full)
#pragma unroll
                for (int i = 0; i < 4; i++) al[i] = *(const float4*)(apl + kk + 4 * i);
#pragma unroll
            for (int i = 0; i < 4; i++) x[i] = *(const float4*)(xp + kk + 4 * i);
        }
#pragma unroll
        for (int k8 = 0; k8 < KC; k8 += 8) {
            uint32_t ahf[4][4], bhf[4][2];
#pragma unroll
            for (int mi = 0; mi < 4; mi++) {
                int r0 = wm * 64 + mi * 16 + g;
                float2 t0 = *(const float2*)&Ah[ab + r0 * LDA + k8 + 2 * c];
                float2 t1 = *(const float2*)&Ah[ab + (r0 + 8) * LDA + k8 + 2 * c];
                ahf[mi][0] = __float_as_uint(t0.x);
                ahf[mi][1] = __float_as_uint(t1.x);
                ahf[mi][2] = __float_as_uint(t0.y);
                ahf[mi][3] = __float_as_uint(t1.y);
            }
#pragma unroll
            for (int ni = 0; ni < 4; ni++) {
                int n0 = wn * 32 + ni * 8 + g;
                float2 t = *(const float2*)&Xh[ab + n0 * LDA + k8 + 2 * c];
                bhf[ni][0] = __float_as_uint(t.x);
                bhf[ni][1] = __float_as_uint(t.y);
            }
            if (full) {
                uint32_t alf[4][4], blf[4][2];
#pragma unroll
                for (int mi = 0; mi < 4; mi++) {
                    int r0 = wm * 64 + mi * 16 + g;
                    float2 t0 = *(const float2*)&Al[ab + r0 * LDA + k8 + 2 * c];
                    float2 t1 = *(const float2*)&Al[ab + (r0 + 8) * LDA + k8 + 2 * c];
                    alf[mi][0] = __float_as_uint(t0.x);
                    alf[mi][1] = __float_as_uint(t1.x);
                    alf[mi][2] = __float_as_uint(t0.y);
                    alf[mi][3] = __float_as_uint(t1.y);
                }
#pragma unroll
                for (int ni = 0; ni < 4; ni++) {
                    int n0 = wn * 32 + ni * 8 + g;
                    float2 t = *(const float2*)&Xl[ab + n0 * LDA + k8 + 2 * c];
                    blf[ni][0] = __float_as_uint(t.x);
                    blf[ni][1] = __float_as_uint(t.y);
                }
#pragma unroll
                for (int mi = 0; mi < 4; mi++)
#pragma unroll
                    for (int ni = 0; ni < 4; ni++) {
                        mma8(acc[mi][ni], ahf[mi], bhf[ni]);
                        mma8(acc[mi][ni], ahf[mi], blf[ni]);
                        mma8(acc[mi][ni], alf[mi], bhf[ni]);
                    }
            } else {
#pragma unroll
                for (int mi = 0; mi < 4; mi++)
#pragma unroll
                    for (int ni = 0; ni < 4; ni++)
                        mma8(acc[mi][ni], ahf[mi], bhf[ni]);
            }
        }
        if (s + 1 < NST) {
            int nb = (buf ^ 1) * SM_BUF + sbase;
            if (PRESPLIT) {
                perm_st(Ah, nb, a[0], a[1]);
                perm_st(Ah, nb + 8, a[2], a[3]);
                if (full) {
                    perm_st(Al, nb, al[0], al[1]);
                    perm_st(Al, nb + 8, al[2], al[3]);
                }
            } else {
                perm_split(Ah, Al, nb, a[0], a[1], full);
                perm_split(Ah, Al, nb + 8, a[2], a[3], full);
            }
            perm_split(Xh, Xl, nb, x[0], x[1], full);
            perm_split(Xh, Xl, nb + 8, x[2], x[3], full);
        }
        __syncthreads();
    }
}

// ---------------- init ----------------
__global__ void init_kernel() {
    int t = threadIdx.x;
    for (int i = t; i < MAXIT; i += 256) g_md[i] = 0u;
    if (t == 0) { g_barcnt = 0u; g_resid = 0; g_x0nz = 0u; }
}

// ---------------- projection of A + tf32 hi/lo presplit ----------------
__global__ __launch_bounds__(256) void project_kernel(const float* __restrict__ A) {
    __shared__ float warp_s[8];
    __shared__ float s_scale;
    int row = blockIdx.x;
    const float* ar = A + (size_t)row * N_DIM;
    float s = 0.f;
    for (int c = threadIdx.x; c < N_DIM; c += 256) s += fabsf(ar[c]);
#pragma unroll
    for (int o = 16; o; o >>= 1) s += __shfl_xor_sync(0xffffffffu, s, o);
    if ((threadIdx.x & 31) == 0) warp_s[threadIdx.x >> 5] = s;
    __syncthreads();
    if (threadIdx.x == 0) {
        float t = 0.f;
#pragma unroll
        for (int i = 0; i < 8; i++) t += warp_s[i];
        s_scale = fminf(1.f, KAPPA / fmaxf(t, 1e-12f));
    }
    __syncthreads();
    float sc = s_scale;
    float* oh = g_Ahi + (size_t)row * N_DIM;
    float* ol = g_Alo + (size_t)row * N_DIM;
    for (int c = threadIdx.x; c < N_DIM; c += 256) {
        float v = ar[c] * sc;
        float h = tf(v);
        oh[c] = h;
        ol[c] = tf(v - h);
    }
}

// ---------------- X0 copy + nonzero detect ----------------
__global__ void copyx0_kernel(const float* __restrict__ in) {
    size_t idx = (size_t)blockIdx.x * 256 + threadIdx.x;
    const float4* src = (const float4*)in;
    float4* dst = (float4*)g_X0buf;
    size_t tot = (size_t)M_DIM * N_DIM / 4;
    unsigned nz = 0u;
    for (size_t i = idx; i < tot; i += (size_t)gridDim.x * 256) {
        float4 v = src[i];
        dst[i] = v;
        nz |= __float_as_uint(v.x) | __float_as_uint(v.y)
            | __float_as_uint(v.z) | __float_as_uint(v.w);
    }
    nz &= 0x7FFFFFFFu;   // ignore -0
#pragma unroll
    for (int o = 16; o; o >>= 1) nz |= __shfl_xor_sync(0xffffffffu, nz, o);
    if ((threadIdx.x & 31) == 0 && nz) atomicOr(&g_x0nz, 1u);
}

// ---------------- BU[j][i] = sum_p B[i,p] U[j,p] via 3xTF32 tensor tile ----------------
__global__ __launch_bounds__(256, 1) void bu_kernel_t(const float* __restrict__ B,
                                                      const float* __restrict__ U) {
    extern __shared__ float sm[];
    int bid = blockIdx.x;
    int j0 = (bid & 15) * 128;
    int i0 = (bid >> 4) * 128;
    float acc[4][4][4];
#pragma unroll
    for (int mi = 0; mi < 4; mi++)
#pragma unroll
        for (int ni = 0; ni < 4; ni++)
#pragma unroll
            for (int r = 0; r < 4; r++) acc[mi][ni][r] = 0.f;
    gemm_tile<0>(B + (size_t)i0 * P_DIM, B + (size_t)i0 * P_DIM, P_DIM,
                 U + (size_t)j0 * P_DIM, P_DIM, P_DIM, 1, sm, acc);

    int warp = threadIdx.x >> 5, lane = threadIdx.x & 31;
    int wm = warp >> 2, wn = warp & 3;
    int g = lane >> 2, c = lane & 3;
#pragma unroll
    for (int mi = 0; mi < 4; mi++)
#pragma unroll
        for (int ni = 0; ni < 4; ni++)
#pragma unroll
            for (int r = 0; r < 4; r++) {
                int il = wm * 64 + mi * 16 + g + ((r >= 2) ? 8 : 0);
                int jl = wn * 32 + ni * 8 + 2 * c + (r & 1);
                g_BU[(size_t)(j0 + jl) * N_DIM + (i0 + il)] = acc[mi][ni][r];
            }
}

// ---------------- persistent hybrid Picard loop ----------------
__global__ __launch_bounds__(256, 1) void picard_kernel() {
    extern __shared__ float sm[];
    __shared__ float red[8];

    int tid = threadIdx.x;
    int warp = tid >> 5, lane = tid & 31;
    int wm = warp >> 2, wn = warp & 3;
    int g = lane >> 2, c = lane & 3;
    int bid = blockIdx.x;
    int j0 = (bid & 15) * 128;   // m tile
    int i0 = (bid >> 4) * 128;   // n tile

    float* Xb[2] = {g_X0buf, g_X1buf};
    float* Dd[2] = {g_dX0, g_dX1};
    unsigned x0nz = g_x0nz;      // uniform across grid (set before launch)

    int phase = 0;      // 0 = fast X, 1 = refresh, 2 = residual
    int curX = 0, curD = 0, base = 0;
    float* fin1 = g_X0buf;
    float* fin2 = g_X0buf;
    int finR = 0;

    for (int it = 0; it < MAXIT; it++) {
        int mode = phase;
        const float* __restrict__ in = (mode == 2) ? Dd[curD] : Xb[curX];
        float* __restrict__ out = (mode == 0) ? Xb[curX ^ 1]
                                 : (mode == 1) ? Dd[0] : Dd[curD ^ 1];
        int full = (mode == 1);
        const float* __restrict__ Xbase = Xb[(mode == 1) ? curX : base];

        float acc[4][4][4];
#pragma unroll
        for (int mi = 0; mi < 4; mi++)
#pragma unroll
            for (int ni = 0; ni < 4; ni++)
#pragma unroll
                for (int r = 0; r < 4; r++) acc[mi][ni][r] = 0.f;

        int skip_gemm = (it == 0 && mode == 0 && !x0nz);  // A @ 0 == 0 exactly
        if (!skip_gemm)
            gemm_tile<1>(g_Ahi + (size_t)i0 * N_DIM, g_Alo + (size_t)i0 * N_DIM, N_DIM,
                         in + (size_t)j0 * N_DIM, N_DIM, N_DIM, full, sm, acc);

        // epilogue
        float maxd = 0.f;
#pragma unroll
        for (int mi = 0; mi < 4; mi++)
#pragma unroll
            for (int ni = 0; ni < 4; ni++)
#pragma unroll
                for (int r = 0; r < 4; r++) {
                    int il = wm * 64 + mi * 16 + g + ((r >= 2) ? 8 : 0);
                    int jl = wn * 32 + ni * 8 + 2 * c + (r & 1);
                    size_t adr = (size_t)(j0 + jl) * N_DIM + (i0 + il);
                    float a = acc[mi][ni][r];
                    if (mode == 0) {
                        float v = fmaxf(a + g_BU[adr], 0.f);
                        maxd = fmaxf(maxd, fabsf(v - in[adr]));
                        out[adr] = v;
                    } else if (mode == 1) {
                        float t = a + g_BU[adr];
                        g_Y0[adr] = t;
                        float v = fmaxf(t, 0.f);
                        float d = v - in[adr];      // Xbase == in
                        maxd = fmaxf(maxd, fabsf(d));
                        out[adr] = d;
                    } else {
                        float v = fmaxf(a + g_Y0[adr], 0.f);
                        float d = v - Xbase[adr];
                        maxd = fmaxf(maxd, fabsf(d - in[adr]));
                        out[adr] = d;
                    }
                }
#pragma unroll
        for (int o = 16; o; o >>= 1) maxd = fmaxf(maxd, __shfl_xor_sync(0xffffffffu, maxd, o));
        if (lane == 0) red[warp] = maxd;
        __syncthreads();
        if (tid == 0) {
            float m = red[0];
#pragma unroll
            for (int i2 = 1; i2 < 8; i2++) m = fmaxf(m, red[i2]);
            atomicMax(&g_md[it], __float_as_uint(m));
        }
        __syncthreads();

        // software grid barrier (128 blocks co-resident on 148 SMs)
        if (tid == 0) {
            __threadfence();
            atomicAdd(&g_barcnt, 1u);
            unsigned target = (unsigned)(it + 1) * NBLK;
            while (atomicAdd(&g_barcnt, 0u) < target) {}
            __threadfence();
        }
        __syncthreads();

        float md = __uint_as_float(g_md[it]);
        fin1 = (mode == 0) ? out : (float*)Xbase;
        fin2 = out;
        finR = (mode >= 1);
        if (md <= TOL) break;

        if (mode == 0) {
            curX ^= 1;
            if (md <= SWITCH_MD) phase = 1;
        } else if (mode == 1) {
            base = curX;
            phase = 2;
            curD = 0;
        } else {
            curD ^= 1;
        }
    }

    if (bid == 0 && tid == 0) {
        g_fp1 = fin1;
        g_fp2 = fin2;
        g_resid = finR;
    }
}

// ---------------- final: k-split x8 partials; X = fp1 (+ fp2 if resid) ----------------
__global__ __launch_bounds__(256) void final_part_kernel(const float* __restrict__ Cm,
                                                         const float* __restrict__ Dm,
                                                         const float* __restrict__ U) {
    const float* __restrict__ F1 = g_fp1;
    const float* __restrict__ F2 = g_fp2;
    int resid = g_resid;
    __shared__ float As[16][132];
    __shared__ float Bs[16][132];
    int j0 = blockIdx.x * 128;
    int part = blockIdx.y;      // 0..7
    int tid = threadIdx.x;
    int lk = tid & 15, lb = tid >> 4;
    int tx = tid & 15, ty = tid >> 4;
    float acc[8][8] = {};

    int n_lo = part * (N_DIM / 8), n_hi = n_lo + N_DIM / 8;
    for (int kk = n_lo; kk < n_hi; kk += 16) {
        __syncthreads();
#pragma unroll
        for (int r = 0; r < 8; r++) {
            As[lk][lb + 16 * r] = Cm[(size_t)(lb + 16 * r) * N_DIM + kk + lk];
            size_t off = (size_t)(j0 + lb + 16 * r) * N_DIM + kk + lk;
            float xv = F1[off];
            if (resid) xv += F2[off];
            Bs[lk][lb + 16 * r] = xv;
        }
        __syncthreads();
#pragma unroll
        for (int k = 0; k < 16; k++) {
            float a[8], b[8];
#pragma unroll
            for (int i = 0; i < 8; i++) a[i] = As[k][ty * 8 + i];
#pragma unroll
            for (int j = 0; j < 8; j++) b[j] = Bs[k][tx * 8 + j];
#pragma unroll
            for (int i = 0; i < 8; i++)
#pragma unroll
                for (int j = 0; j < 8; j++) acc[i][j] = fmaf(a[i], b[j], acc[i][j]);
        }
    }
    int p_lo = part * (P_DIM / 8), p_hi = p_lo + P_DIM / 8;
    for (int kk = p_lo; kk < p_hi; kk += 16) {
        __syncthreads();
#pragma unroll
        for (int r = 0; r < 8; r++) {
            As[lk][lb + 16 * r] = Dm[(size_t)(lb + 16 * r) * P_DIM + kk + lk];
            Bs[lk][lb + 16 * r] = U[(size_t)(j0 + lb + 16 * r) * P_DIM + kk + lk];
        }
        __syncthreads();
#pragma unroll
        for (int k = 0; k < 16; k++) {
            float a[8], b[8];
#pragma unroll
            for (int i = 0; i < 8; i++) a[i] = As[k][ty * 8 + i];
#pragma unroll
            for (int j = 0; j < 8; j++) b[j] = Bs[k][tx * 8 + j];
#pragma unroll
            for (int i = 0; i < 8; i++)
#pragma unroll
                for (int j = 0; j < 8; j++) acc[i][j] = fmaf(a[i], b[j], acc[i][j]);
        }
    }
    float* outp = g_part[part];
#pragma unroll
    for (int j = 0; j < 8; j++) {
        size_t off = (size_t)(j0 + tx * 8 + j) * Q_DIM + ty * 8;
        *(float4*)(outp + off)     = make_float4(acc[0][j], acc[1][j], acc[2][j], acc[3][j]);
        *(float4*)(outp + off + 4) = make_float4(acc[4][j], acc[5][j], acc[6][j], acc[7][j]);
    }
}

__global__ void final_reduce_kernel(float* __restrict__ outp) {
    size_t idx = (size_t)blockIdx.x * 256 + threadIdx.x;
    size_t tot = (size_t)M_DIM * Q_DIM / 4;
    float4* o = (float4*)outp;
    for (size_t i = idx; i < tot; i += (size_t)gridDim.x * 256) {
        float4 s = ((const float4*)g_part[0])[i];
#pragma unroll
        for (int p = 1; p < 8; p++) {
            float4 v = ((const float4*)g_part[p])[i];
            s.x += v.x; s.y += v.y; s.z += v.z; s.w += v.w;
        }
        o[i] = s;
    }
}

// ---------------- launcher ----------------
extern "C" void kernel_launch(void* const* d_in, const int* in_sizes, int n_in,
                              void* d_out, int out_size) {
    (void)in_sizes; (void)n_in; (void)out_size;
    const float* U  = (const float*)d_in[0];
    const float* X0 = (const float*)d_in[1];
    const float* A  = (const float*)d_in[2];
    const float* B  = (const float*)d_in[3];
    const float* Cm = (const float*)d_in[4];
    const float* Dm = (const float*)d_in[5];
    float* outp = (float*)d_out;

    cudaFuncSetAttribute(picard_kernel, cudaFuncAttributeMaxDynamicSharedMemorySize, DSMEM_BYTES);
    cudaFuncSetAttribute(bu_kernel_t, cudaFuncAttributeMaxDynamicSharedMemorySize, DSMEM_BYTES);

    init_kernel<<<1, 256>>>();
    project_kernel<<<N_DIM, 256>>>(A);
    copyx0_kernel<<<512, 256>>>(X0);
    bu_kernel_t<<<NBLK, 256, DSMEM_BYTES>>>(B, U);
    picard_kernel<<<NBLK, 256, DSMEM_BYTES>>>();
    final_part_kernel<<<dim3(M_DIM / 128, 8), 256>>>(Cm, Dm, U);
    final_reduce_kernel<<<64, 256>>>(outp);
}

// round 10
// speedup vs baseline: 1.7984x; 1.2747x over previous
#include <cuda_runtime.h>
#include <cstdint>

#define N_DIM 1024
#define M_DIM 2048
#define P_DIM 512
#define Q_DIM 128
#define KAPPA 0.99f
#define TOL   3e-6f
#define MAXIT 300
#define NBLK  128

#define KC   32
#define LDA  40                  // row stride (floats): LDS.64 fragment phases conflict-free
#define SM_BUF 5120              // 128 * LDA floats per buffer
// layout (floats): Ah[2] @0, Al[2] @10240, Xh[2] @20480, Xl[2] @30720
#define DSMEM_BYTES (40960 * 4)

// ---------------- device state ----------------
__device__ float g_Ahi[(size_t)N_DIM * N_DIM];
__device__ float g_Alo[(size_t)N_DIM * N_DIM];
__device__ float g_BU[(size_t)M_DIM * N_DIM];     // m-major
__device__ float g_X0buf[(size_t)M_DIM * N_DIM];  // m-major X ping-pong
__device__ float g_X1buf[(size_t)M_DIM * N_DIM];
__device__ float g_part[8][(size_t)M_DIM * Q_DIM];
__device__ unsigned g_md[MAXIT];
__device__ unsigned g_barcnt;
__device__ unsigned g_x0nz;
__device__ float* g_fp1;

// ---------------- helpers ----------------
__device__ __forceinline__ uint32_t f2tf(float x) {
    uint32_t r;
    asm("cvt.rna.tf32.f32 %0, %1;" : "=r"(r) : "f"(x));
    return r;
}
__device__ __forceinline__ float tf(float x) { return __uint_as_float(f2tf(x)); }

__device__ __forceinline__ void mma8(float* d, const uint32_t* a, const uint32_t* b) {
    asm volatile(
        "mma.sync.aligned.m16n8k8.row.col.f32.tf32.tf32.f32 "
        "{%0,%1,%2,%3},{%4,%5,%6,%7},{%8,%9},{%0,%1,%2,%3};"
        : "+f"(d[0]), "+f"(d[1]), "+f"(d[2]), "+f"(d[3])
        : "r"(a[0]), "r"(a[1]), "r"(a[2]), "r"(a[3]), "r"(b[0]), "r"(b[1]));
}

// interleaved store: within 8-col block, col j -> 2*(j&3)+(j>>2)
__device__ __forceinline__ void perm_st(float* dst, int off, float4 v0, float4 v1) {
    *(float4*)&dst[off]     = make_float4(v0.x, v1.x, v0.y, v1.y);
    *(float4*)&dst[off + 4] = make_float4(v0.z, v1.z, v0.w, v1.w);
}
__device__ __forceinline__ void perm_split(float* hi, float* lo, int off,
                                           float4 v0, float4 v1, int full) {
    float4 h0 = make_float4(tf(v0.x), tf(v0.y), tf(v0.z), tf(v0.w));
    float4 h1 = make_float4(tf(v1.x), tf(v1.y), tf(v1.z), tf(v1.w));
    perm_st(hi, off, h0, h1);
    if (full) {
        float4 l0 = make_float4(tf(v0.x - h0.x), tf(v0.y - h0.y),
                                tf(v0.z - h0.z), tf(v0.w - h0.w));
        float4 l1 = make_float4(tf(v1.x - h1.x), tf(v1.y - h1.y),
                                tf(v1.z - h1.z), tf(v1.w - h1.w));
        perm_st(lo, off, l0, l1);
    }
}

// ---------------- 128x128 GEMM tile: acc += Ab(128,k) * Bb(128,k)^T, KC=32 ----------------
template <int PRESPLIT>
__device__ __forceinline__ void gemm_tile(
    const float* __restrict__ Ahi, const float* __restrict__ Alo, int lda,
    const float* __restrict__ Bb, int ldb, int kdim, int full,
    float* __restrict__ sm, float acc[4][4][4])
{
    float* Ah = sm;
    float* Al = sm + 10240;
    float* Xh = sm + 20480;
    float* Xl = sm + 30720;
    int tid = threadIdx.x;
    int warp = tid >> 5, lane = tid & 31;
    int wm = warp >> 2, wn = warp & 3;
    int g = lane >> 2, c = lane & 3;
    int lrow = tid & 127, lh = tid >> 7;       // col half: lh*16
    int sbase = lrow * LDA + lh * 16;

    const float* aph = Ahi + (size_t)lrow * lda + lh * 16;
    const float* apl = Alo + (size_t)lrow * lda + lh * 16;
    const float* xp  = Bb  + (size_t)lrow * ldb + lh * 16;

    float4 a[4], al[4], x[4];
#pragma unroll
    for (int i = 0; i < 4; i++) a[i] = *(const float4*)(aph + 4 * i);
    if (PRESPLIT && full)
#pragma unroll
        for (int i = 0; i < 4; i++) al[i] = *(const float4*)(apl + 4 * i);
#pragma unroll
    for (int i = 0; i < 4; i++) x[i] = *(const float4*)(xp + 4 * i);

    if (PRESPLIT) {
        perm_st(Ah, sbase, a[0], a[1]);
        perm_st(Ah, sbase + 8, a[2], a[3]);
        if (full) {
            perm_st(Al, sbase, al[0], al[1]);
            perm_st(Al, sbase + 8, al[2], al[3]);
        }
    } else {
        perm_split(Ah, Al, sbase, a[0], a[1], full);
        perm_split(Ah, Al, sbase + 8, a[2], a[3], full);
    }
    perm_split(Xh, Xl, sbase, x[0], x[1], full);
    perm_split(Xh, Xl, sbase + 8, x[2], x[3], full);
    __syncthreads();

    int NST = kdim / KC;
    for (int s = 0; s < NST; s++) {
        int buf = s & 1;
        int ab = buf * SM_BUF;
        if (s + 1 < NST) {
            int kk = KC * (s + 1);
#pragma unroll
            for (int i = 0; i < 4; i++) a[i] = *(const float4*)(aph + kk + 4 * i);
            if (PRESPLIT && full)
#pragma unroll
                for (int i = 0; i < 4; i++) al[i] = *(const float4*)(apl + kk + 4 * i);
#pragma unroll
            for (int i = 0; i < 4; i++) x[i] = *(const float4*)(xp + kk + 4 * i);
        }
#pragma unroll
        for (int k8 = 0; k8 < KC; k8 += 8) {
            uint32_t ahf[4][4], bhf[4][2];
#pragma unroll
            for (int mi = 0; mi < 4; mi++) {
                int r0 = wm * 64 + mi * 16 + g;
                float2 t0 = *(const float2*)&Ah[ab + r0 * LDA + k8 + 2 * c];
                float2 t1 = *(const float2*)&Ah[ab + (r0 + 8) * LDA + k8 + 2 * c];
                ahf[mi][0] = __float_as_uint(t0.x);
                ahf[mi][1] = __float_as_uint(t1.x);
                ahf[mi][2] = __float_as_uint(t0.y);
                ahf[mi][3] = __float_as_uint(t1.y);
            }
#pragma unroll
            for (int ni = 0; ni < 4; ni++) {
                int n0 = wn * 32 + ni * 8 + g;
                float2 t = *(const float2*)&Xh[ab + n0 * LDA + k8 + 2 * c];
                bhf[ni][0] = __float_as_uint(t.x);
                bhf[ni][1] = __float_as_uint(t.y);
            }
            if (full) {
                uint32_t alf[4][4], blf[4][2];
#pragma unroll
                for (int mi = 0; mi < 4; mi++) {
                    int r0 = wm * 64 + mi * 16 + g;
                    float2 t0 = *(const float2*)&Al[ab + r0 * LDA + k8 + 2 * c];
                    float2 t1 = *(const float2*)&Al[ab + (r0 + 8) * LDA + k8 + 2 * c];
                    alf[mi][0] = __float_as_uint(t0.x);
                    alf[mi][1] = __float_as_uint(t1.x);
                    alf[mi][2] = __float_as_uint(t0.y);
                    alf[mi][3] = __float_as_uint(t1.y);
                }
#pragma unroll
                for (int ni = 0; ni < 4; ni++) {
                    int n0 = wn * 32 + ni * 8 + g;
                    float2 t = *(const float2*)&Xl[ab + n0 * LDA + k8 + 2 * c];
                    blf[ni][0] = __float_as_uint(t.x);
                    blf[ni][1] = __float_as_uint(t.y);
                }
#pragma unroll
                for (int mi = 0; mi < 4; mi++)
#pragma unroll
                    for (int ni = 0; ni < 4; ni++) {
                        mma8(acc[mi][ni], ahf[mi], bhf[ni]);
                        mma8(acc[mi][ni], ahf[mi], blf[ni]);
                        mma8(acc[mi][ni], alf[mi], bhf[ni]);
                    }
            } else {
#pragma unroll
                for (int mi = 0; mi < 4; mi++)
#pragma unroll
                    for (int ni = 0; ni < 4; ni++)
                        mma8(acc[mi][ni], ahf[mi], bhf[ni]);
            }
        }
        if (s + 1 < NST) {
            int nb = (buf ^ 1) * SM_BUF + sbase;
            if (PRESPLIT) {
                perm_st(Ah, nb, a[0], a[1]);
                perm_st(Ah, nb + 8, a[2], a[3]);
                if (full) {
                    perm_st(Al, nb, al[0], al[1]);
                    perm_st(Al, nb + 8, al[2], al[3]);
                }
            } else {
                perm_split(Ah, Al, nb, a[0], a[1], full);
                perm_split(Ah, Al, nb + 8, a[2], a[3], full);
            }
            perm_split(Xh, Xl, nb, x[0], x[1], full);
            perm_split(Xh, Xl, nb + 8, x[2], x[3], full);
        }
        __syncthreads();
    }
}

// ---------------- init ----------------
__global__ void init_kernel() {
    int t = threadIdx.x;
    for (int i = t; i < MAXIT; i += 256) g_md[i] = 0u;
    if (t == 0) { g_barcnt = 0u; g_x0nz = 0u; }
}

// ---------------- fused prep: project A (8 rows/block) + copy X0 + BU tile ----------------
__global__ __launch_bounds__(256, 1) void prep_kernel(const float* __restrict__ A,
                                                      const float* __restrict__ X0,
                                                      const float* __restrict__ B,
                                                      const float* __restrict__ U) {
    extern __shared__ float sm[];
    int bid = blockIdx.x;
    int tid = threadIdx.x;
    int warp = tid >> 5, lane = tid & 31;

    // --- part 1: L-inf projection + tf32 presplit for rows [bid*8, bid*8+8) ---
    {
        int row = bid * 8 + warp;
        const float* ar = A + (size_t)row * N_DIM;
        float s = 0.f;
#pragma unroll
        for (int c = lane; c < N_DIM; c += 32) s += fabsf(ar[c]);
#pragma unroll
        for (int o = 16; o; o >>= 1) s += __shfl_xor_sync(0xffffffffu, s, o);
        float sc = fminf(1.f, KAPPA / fmaxf(s, 1e-12f));
        float* oh = g_Ahi + (size_t)row * N_DIM;
        float* ol = g_Alo + (size_t)row * N_DIM;
#pragma unroll
        for (int c = lane; c < N_DIM; c += 32) {
            float v = ar[c] * sc;
            float h = tf(v);
            oh[c] = h;
            ol[c] = tf(v - h);
        }
    }

    // --- part 2: copy X0 slice + nonzero detect ---
    {
        size_t base = (size_t)bid * 4096;   // float4 units; 128 blocks x 4096 = 2M/4
        const float4* src = (const float4*)X0;
        float4* dst = (float4*)g_X0buf;
        unsigned nz = 0u;
        for (int i = tid; i < 4096; i += 256) {
            float4 v = src[base + i];
            dst[base + i] = v;
            nz |= __float_as_uint(v.x) | __float_as_uint(v.y)
                | __float_as_uint(v.z) | __float_as_uint(v.w);
        }
        nz &= 0x7FFFFFFFu;
#pragma unroll
        for (int o = 16; o; o >>= 1) nz |= __shfl_xor_sync(0xffffffffu, nz, o);
        if (lane == 0 && nz) atomicOr(&g_x0nz, 1u);
    }

    // --- part 3: BU tile (full 3xTF32) ---
    int j0 = (bid & 15) * 128;
    int i0 = (bid >> 4) * 128;
    float acc[4][4][4];
#pragma unroll
    for (int mi = 0; mi < 4; mi++)
#pragma unroll
        for (int ni = 0; ni < 4; ni++)
#pragma unroll
            for (int r = 0; r < 4; r++) acc[mi][ni][r] = 0.f;
    gemm_tile<0>(B + (size_t)i0 * P_DIM, B + (size_t)i0 * P_DIM, P_DIM,
                 U + (size_t)j0 * P_DIM, P_DIM, P_DIM, 1, sm, acc);

    int wm = warp >> 2, wn = warp & 3;
    int g = lane >> 2, c = lane & 3;
#pragma unroll
    for (int mi = 0; mi < 4; mi++)
#pragma unroll
        for (int ni = 0; ni < 4; ni++)
#pragma unroll
            for (int r = 0; r < 4; r++) {
                int il = wm * 64 + mi * 16 + g + ((r >= 2) ? 8 : 0);
                int jl = wn * 32 + ni * 8 + 2 * c + (r & 1);
                g_BU[(size_t)(j0 + jl) * N_DIM + (i0 + il)] = acc[mi][ni][r];
            }
}

// ---------------- persistent hi-only TF32 Picard loop ----------------
__global__ __launch_bounds__(256, 1) void picard_kernel() {
    extern __shared__ float sm[];
    __shared__ float red[8];

    int tid = threadIdx.x;
    int warp = tid >> 5, lane = tid & 31;
    int wm = warp >> 2, wn = warp & 3;
    int g = lane >> 2, c = lane & 3;
    int bid = blockIdx.x;
    int j0 = (bid & 15) * 128;   // m tile
    int i0 = (bid >> 4) * 128;   // n tile

    float* Xb[2] = {g_X0buf, g_X1buf};
    unsigned x0nz = g_x0nz;
    int cur = 0;
    float* fin = g_X0buf;

    for (int it = 0; it < MAXIT; it++) {
        const float* __restrict__ in = Xb[cur];
        float* __restrict__ out = Xb[cur ^ 1];

        float acc[4][4][4];
#pragma unroll
        for (int mi = 0; mi < 4; mi++)
#pragma unroll
            for (int ni = 0; ni < 4; ni++)
#pragma unroll
                for (int r = 0; r < 4; r++) acc[mi][ni][r] = 0.f;

        if (!(it == 0 && !x0nz))   // A @ 0 == 0 exactly
            gemm_tile<1>(g_Ahi + (size_t)i0 * N_DIM, g_Alo + (size_t)i0 * N_DIM, N_DIM,
                         in + (size_t)j0 * N_DIM, N_DIM, N_DIM, 0, sm, acc);

        // epilogue: X_out = relu(A@X_in + BU), maxdiff vs X_in
        float maxd = 0.f;
#pragma unroll
        for (int mi = 0; mi < 4; mi++)
#pragma unroll
            for (int ni = 0; ni < 4; ni++)
#pragma unroll
                for (int r = 0; r < 4; r++) {
                    int il = wm * 64 + mi * 16 + g + ((r >= 2) ? 8 : 0);
                    int jl = wn * 32 + ni * 8 + 2 * c + (r & 1);
                    size_t adr = (size_t)(j0 + jl) * N_DIM + (i0 + il);
                    float v = fmaxf(acc[mi][ni][r] + g_BU[adr], 0.f);
                    maxd = fmaxf(maxd, fabsf(v - in[adr]));
                    out[adr] = v;
                }
#pragma unroll
        for (int o = 16; o; o >>= 1) maxd = fmaxf(maxd, __shfl_xor_sync(0xffffffffu, maxd, o));
        if (lane == 0) red[warp] = maxd;
        __syncthreads();
        if (tid == 0) {
            float m = red[0];
#pragma unroll
            for (int i2 = 1; i2 < 8; i2++) m = fmaxf(m, red[i2]);
            atomicMax(&g_md[it], __float_as_uint(m));
        }
        __syncthreads();

        // software grid barrier (128 blocks co-resident on 148 SMs)
        if (tid == 0) {
            __threadfence();
            atomicAdd(&g_barcnt, 1u);
            unsigned target = (unsigned)(it + 1) * NBLK;
            while (atomicAdd(&g_barcnt, 0u) < target) {}
            __threadfence();
        }
        __syncthreads();

        float md = __uint_as_float(g_md[it]);
        fin = out;
        cur ^= 1;
        if (md <= TOL) break;
    }

    if (bid == 0 && tid == 0) g_fp1 = fin;
}

// ---------------- final: k-split x8 partials ----------------
__global__ __launch_bounds__(256) void final_part_kernel(const float* __restrict__ Cm,
                                                         const float* __restrict__ Dm,
                                                         const float* __restrict__ U) {
    const float* __restrict__ F1 = g_fp1;
    __shared__ float As[16][132];
    __shared__ float Bs[16][132];
    int j0 = blockIdx.x * 128;
    int part = blockIdx.y;      // 0..7
    int tid = threadIdx.x;
    int lk = tid & 15, lb = tid >> 4;
    int tx = tid & 15, ty = tid >> 4;
    float acc[8][8] = {};

    int n_lo = part * (N_DIM / 8), n_hi = n_lo + N_DIM / 8;
    for (int kk = n_lo; kk < n_hi; kk += 16) {
        __syncthreads();
#pragma unroll
        for (int r = 0; r < 8; r++) {
            As[lk][lb + 16 * r] = Cm[(size_t)(lb + 16 * r) * N_DIM + kk + lk];
            Bs[lk][lb + 16 * r] = F1[(size_t)(j0 + lb + 16 * r) * N_DIM + kk + lk];
        }
        __syncthreads();
#pragma unroll
        for (int k = 0; k < 16; k++) {
            float a[8], b[8];
#pragma unroll
            for (int i = 0; i < 8; i++) a[i] = As[k][ty * 8 + i];
#pragma unroll
            for (int j = 0; j < 8; j++) b[j] = Bs[k][tx * 8 + j];
#pragma unroll
            for (int i = 0; i < 8; i++)
#pragma unroll
                for (int j = 0; j < 8; j++) acc[i][j] = fmaf(a[i], b[j], acc[i][j]);
        }
    }
    int p_lo = part * (P_DIM / 8), p_hi = p_lo + P_DIM / 8;
    for (int kk = p_lo; kk < p_hi; kk += 16) {
        __syncthreads();
#pragma unroll
        for (int r = 0; r < 8; r++) {
            As[lk][lb + 16 * r] = Dm[(size_t)(lb + 16 * r) * P_DIM + kk + lk];
            Bs[lk][lb + 16 * r] = U[(size_t)(j0 + lb + 16 * r) * P_DIM + kk + lk];
        }
        __syncthreads();
#pragma unroll
        for (int k = 0; k < 16; k++) {
            float a[8], b[8];
#pragma unroll
            for (int i = 0; i < 8; i++) a[i] = As[k][ty * 8 + i];
#pragma unroll
            for (int j = 0; j < 8; j++) b[j] = Bs[k][tx * 8 + j];
#pragma unroll
            for (int i = 0; i < 8; i++)
#pragma unroll
                for (int j = 0; j < 8; j++) acc[i][j] = fmaf(a[i], b[j], acc[i][j]);
        }
    }
    float* outp = g_part[part];
#pragma unroll
    for (int j = 0; j < 8; j++) {
        size_t off = (size_t)(j0 + tx * 8 + j) * Q_DIM + ty * 8;
        *(float4*)(outp + off)     = make_float4(acc[0][j], acc[1][j], acc[2][j], acc[3][j]);
        *(float4*)(outp + off + 4) = make_float4(acc[4][j], acc[5][j], acc[6][j], acc[7][j]);
    }
}

__global__ void final_reduce_kernel(float* __restrict__ outp) {
    size_t idx = (size_t)blockIdx.x * 256 + threadIdx.x;
    size_t tot = (size_t)M_DIM * Q_DIM / 4;
    float4* o = (float4*)outp;
    for (size_t i = idx; i < tot; i += (size_t)gridDim.x * 256) {
        float4 s = ((const float4*)g_part[0])[i];
#pragma unroll
        for (int p = 1; p < 8; p++) {
            float4 v = ((const float4*)g_part[p])[i];
            s.x += v.x; s.y += v.y; s.z += v.z; s.w += v.w;
        }
        o[i] = s;
    }
}

// ---------------- launcher ----------------
extern "C" void kernel_launch(void* const* d_in, const int* in_sizes, int n_in,
                              void* d_out, int out_size) {
    (void)in_sizes; (void)n_in; (void)out_size;
    const float* U  = (const float*)d_in[0];
    const float* X0 = (const float*)d_in[1];
    const float* A  = (const float*)d_in[2];
    const float* B  = (const float*)d_in[3];
    const float* Cm = (const float*)d_in[4];
    const float* Dm = (const float*)d_in[5];
    float* outp = (float*)d_out;

    cudaFuncSetAttribute(picard_kernel, cudaFuncAttributeMaxDynamicSharedMemorySize, DSMEM_BYTES);
    cudaFuncSetAttribute(prep_kernel, cudaFuncAttributeMaxDynamicSharedMemorySize, DSMEM_BYTES);

    init_kernel<<<1, 256>>>();
    prep_kernel<<<NBLK, 256, DSMEM_BYTES>>>(A, X0, B, U);
    picard_kernel<<<NBLK, 256, DSMEM_BYTES>>>();
    final_part_kernel<<<dim3(M_DIM / 128, 8), 256>>>(Cm, Dm, U);
    final_reduce_kernel<<<64, 256>>>(outp);
}